// round 4
// baseline (speedup 1.0000x reference)
#include <cuda_runtime.h>
#include <cuda_fp16.h>
#include <math.h>

#define NN  50000   // nodes
#define EE  800000  // edges
#define LL  100000  // label edges
#define HH  8       // heads
#define FD  32      // hidden
#define HC  256     // H*C
#define CACHE 128   // per-warp cached edges (deg fallback handles more)

// ---------------- scratch (device globals) --------------------------------------
__device__ float  g_x[NN * FD];
__device__ __half g_hh[(size_t)NN * HC];
__device__ float  g_alsrc[NN * HH];
__device__ float  g_aldst[NN * HH];
__device__ float  g_agg[(size_t)NN * HC];
__device__ float  g_x5[NN * HH];
__device__ float  g_Psrc[2][FD * HH];
__device__ float  g_Pdst[2][FD * HH];
__device__ float  g_M[2][HH * HH];
// CSR by destination
__device__ int g_deg[NN];
__device__ int g_rowptr[NN + 1];
__device__ int g_cursor[NN];
__device__ int g_srcp[EE];   // src node per CSR slot
__device__ int g_eorig[EE];  // original edge id per CSR slot

__device__ __forceinline__ float sel8(const float v[8], int i) {
    float r = v[0];
    #pragma unroll
    for (int k = 1; k < 8; k++) r = (i == k) ? v[k] : r;
    return r;
}

// ---------------- precompute both layers: P_src/P_dst [32,8], M [8,8] ----------
__global__ void k_precompute(const float* __restrict__ W1,  const float* __restrict__ as1,
                             const float* __restrict__ ad1, const float* __restrict__ We1,
                             const float* __restrict__ ae1,
                             const float* __restrict__ W2,  const float* __restrict__ as2,
                             const float* __restrict__ ad2, const float* __restrict__ We2,
                             const float* __restrict__ ae2)
{
    int layer = blockIdx.x;
    const float* W   = layer ? W2  : W1;
    const float* a_s = layer ? as2 : as1;
    const float* a_d = layer ? ad2 : ad1;
    const float* We  = layer ? We2 : We1;
    const float* a_e = layer ? ae2 : ae1;

    int t = threadIdx.x;           // 256 threads
    int f = t >> 3, h = t & 7;
    float ss = 0.f, sd = 0.f;
    #pragma unroll 8
    for (int c = 0; c < FD; c++) {
        float w = W[f * HC + h * FD + c];
        ss = fmaf(w, a_s[h * FD + c], ss);
        sd = fmaf(w, a_d[h * FD + c], sd);
    }
    g_Psrc[layer][f * HH + h] = ss;
    g_Pdst[layer][f * HH + h] = sd;
    if (t < 64) {
        int k = t >> 3;
        float sm = 0.f;
        #pragma unroll 8
        for (int c = 0; c < FD; c++)
            sm = fmaf(We[k * HC + h * FD + c], a_e[h * FD + c], sm);
        g_M[layer][k * HH + h] = sm;
    }
}

// ---------------- CSR build -----------------------------------------------------
__global__ void k_zero_deg(void) {
    int i = blockIdx.x * 256 + threadIdx.x;
    if (i < NN) g_deg[i] = 0;
}
__global__ void k_hist(const int* __restrict__ dst) {
    int e = blockIdx.x * 256 + threadIdx.x;
    if (e < EE) atomicAdd(&g_deg[dst[e]], 1);
}
__global__ void __launch_bounds__(1024)
k_scan(void) {
    const int CH = (NN + 1023) / 1024;   // 49
    __shared__ int sums[1024];
    int t = threadIdx.x;
    int base = t * CH;
    int s = 0;
    for (int i = 0; i < CH; i++) {
        int idx = base + i;
        if (idx < NN) s += g_deg[idx];
    }
    sums[t] = s;
    __syncthreads();
    for (int off = 1; off < 1024; off <<= 1) {
        int v = (t >= off) ? sums[t - off] : 0;
        __syncthreads();
        sums[t] += v;
        __syncthreads();
    }
    int run = (t > 0) ? sums[t - 1] : 0;
    for (int i = 0; i < CH; i++) {
        int idx = base + i;
        if (idx < NN) {
            g_rowptr[idx] = run;
            g_cursor[idx] = run;
            run += g_deg[idx];
        }
    }
    if (t == 1023) g_rowptr[NN] = run;
}
__global__ void k_scatter(const int* __restrict__ src, const int* __restrict__ dst) {
    int e = blockIdx.x * 256 + threadIdx.x;
    if (e >= EE) return;
    int d = dst[e];
    int slot = atomicAdd(&g_cursor[d], 1);
    g_srcp[slot]  = src[e];
    g_eorig[slot] = e;
}

// ---------------- node transform: h = x@W (fp16), al_src/al_dst ----------------
__global__ void __launch_bounds__(256)
k_node(const float* __restrict__ xin, const int* __restrict__ ids,
       const float* __restrict__ W, int layer)
{
    __shared__ float Ws[FD * HC];      // 32KB
    __shared__ float xs[32 * 36];
    __shared__ float Ps[FD * HH], Pd[FD * HH];
    int t  = threadIdx.x;
    int n0 = blockIdx.x * 32;

    for (int i = t; i < FD * HC; i += 256) Ws[i] = W[i];
    Ps[t] = g_Psrc[layer][t];
    Pd[t] = g_Pdst[layer][t];
    const float* xp = xin ? xin : g_x;
    for (int i = t; i < 32 * FD; i += 256) {
        int n = i >> 5, k = i & 31;
        int node = n0 + n;
        float v = 0.f;
        if (node < NN) {
            int r = ids ? ids[node] : node;
            v = xp[(size_t)r * FD + k];
        }
        xs[n * 36 + k] = v;
    }
    __syncthreads();

    float acc[32];
    #pragma unroll
    for (int n = 0; n < 32; n++) acc[n] = 0.f;
    #pragma unroll
    for (int kk = 0; kk < 8; kk++) {
        float w0 = Ws[(kk * 4 + 0) * HC + t];
        float w1 = Ws[(kk * 4 + 1) * HC + t];
        float w2 = Ws[(kk * 4 + 2) * HC + t];
        float w3 = Ws[(kk * 4 + 3) * HC + t];
        #pragma unroll
        for (int n = 0; n < 32; n++) {
            float4 xv = *(const float4*)&xs[n * 36 + kk * 4];
            acc[n] = fmaf(xv.x, w0, acc[n]);
            acc[n] = fmaf(xv.y, w1, acc[n]);
            acc[n] = fmaf(xv.z, w2, acc[n]);
            acc[n] = fmaf(xv.w, w3, acc[n]);
        }
    }
    #pragma unroll
    for (int n = 0; n < 32; n++)
        if (n0 + n < NN) g_hh[(size_t)(n0 + n) * HC + t] = __float2half(acc[n]);

    {
        int n = t >> 3, h = t & 7;
        if (n0 + n < NN) {
            float ss = 0.f, sd = 0.f;
            #pragma unroll
            for (int k = 0; k < FD; k++) {
                float xv = xs[n * 36 + k];
                ss = fmaf(xv, Ps[k * HH + h], ss);
                sd = fmaf(xv, Pd[k * HH + h], sd);
            }
            g_alsrc[(n0 + n) * HH + h] = ss;
            g_aldst[(n0 + n) * HH + h] = sd;
        }
    }
}

// ---------------- fused alpha + softmax + aggregation (warp per node) -----------
__global__ void __launch_bounds__(256)
k_fused(const float* __restrict__ ea, int layer)
{
    __shared__ float Ms[64];
    __shared__ float acache[8][CACHE][8];   // 32KB
    __shared__ int   scache[8][CACHE];      // 4KB
    int w    = threadIdx.x >> 5;
    int lane = threadIdx.x & 31;
    if (threadIdx.x < 64) Ms[threadIdx.x] = g_M[layer][threadIdx.x];
    __syncthreads();

    int n = blockIdx.x * 8 + w;
    if (n >= NN) return;
    int r0 = g_rowptr[n], r1 = g_rowptr[n + 1];
    int deg = r1 - r0;

    float acc[8];
    #pragma unroll
    for (int q = 0; q < 8; q++) acc[q] = 0.f;

    if (deg > 0) {
        // al_dst for this node (all lanes keep all 8)
        float ald[8];
        {
            float4 d0 = *(const float4*)(g_aldst + (size_t)n * 8);
            float4 d1 = *(const float4*)(g_aldst + (size_t)n * 8 + 4);
            ald[0] = d0.x; ald[1] = d0.y; ald[2] = d0.z; ald[3] = d0.w;
            ald[4] = d1.x; ald[5] = d1.y; ald[6] = d1.z; ald[7] = d1.w;
        }

        float m[8], sden[8];
        #pragma unroll
        for (int h = 0; h < 8; h++) { m[h] = -1e30f; sden[h] = 0.f; }

        // ---- pass A: lane-parallel alpha compute + online softmax + smem cache
        for (int i = lane; i < deg; i += 32) {
            int p  = r0 + i;
            int eo = g_eorig[p];
            int s  = g_srcp[p];
            float4 e0 = *(const float4*)(ea + (size_t)eo * 8);
            float4 e1 = *(const float4*)(ea + (size_t)eo * 8 + 4);
            float4 s0 = *(const float4*)(g_alsrc + (size_t)s * 8);
            float4 s1 = *(const float4*)(g_alsrc + (size_t)s * 8 + 4);
            float a[8] = { s0.x + ald[0], s0.y + ald[1], s0.z + ald[2], s0.w + ald[3],
                           s1.x + ald[4], s1.y + ald[5], s1.z + ald[6], s1.w + ald[7] };
            float ev[8] = { e0.x, e0.y, e0.z, e0.w, e1.x, e1.y, e1.z, e1.w };
            #pragma unroll
            for (int k = 0; k < 8; k++)
                #pragma unroll
                for (int h = 0; h < 8; h++)
                    a[h] = fmaf(ev[k], Ms[k * 8 + h], a[h]);
            #pragma unroll
            for (int h = 0; h < 8; h++) a[h] = a[h] > 0.f ? a[h] : 0.2f * a[h];

            if (i < CACHE) {
                scache[w][i] = s;
                *(float4*)&acache[w][i][0] = make_float4(a[0], a[1], a[2], a[3]);
                *(float4*)&acache[w][i][4] = make_float4(a[4], a[5], a[6], a[7]);
            }
            #pragma unroll
            for (int h = 0; h < 8; h++) {
                float mn = fmaxf(m[h], a[h]);
                sden[h] = sden[h] * expf(m[h] - mn) + expf(a[h] - mn);
                m[h] = mn;
            }
        }
        // ---- butterfly merge of (m, s) across the warp
        #pragma unroll
        for (int off = 16; off; off >>= 1) {
            #pragma unroll
            for (int h = 0; h < 8; h++) {
                float mo = __shfl_xor_sync(0xffffffffu, m[h], off);
                float so = __shfl_xor_sync(0xffffffffu, sden[h], off);
                float mn = fmaxf(m[h], mo);
                sden[h] = sden[h] * expf(m[h] - mn) + so * expf(mo - mn);
                m[h] = mn;
            }
        }
        __syncwarp();

        // ---- pass C: gather + weighted accumulate
        int head = lane >> 2;          // head for FMA columns (cols lane*8..lane*8+7)
        int eg   = lane >> 3;          // edge subgroup for weight compute
        int hh   = lane & 7;           // head for weight compute
        float m_hd  = sel8(m, head);
        float ri_hd = 1.f / (sel8(sden, head) + 1e-16f);
        float m_hh  = sel8(m, hh);
        float ri_hh = 1.f / (sel8(sden, hh) + 1e-16f);
        float ald_hh = sel8(ald, hh);
        (void)m_hd; (void)ri_hd;

        for (int p4 = 0; p4 < deg; p4 += 4) {
            int pp = p4 + eg;
            float wv = 0.f;
            int   ss = 0;
            if (pp < deg) {
                float a;
                if (pp < CACHE) {
                    a  = acache[w][pp][hh];
                    ss = scache[w][pp];
                } else {
                    int eo = g_eorig[r0 + pp];
                    ss = g_srcp[r0 + pp];
                    float4 e0 = *(const float4*)(ea + (size_t)eo * 8);
                    float4 e1 = *(const float4*)(ea + (size_t)eo * 8 + 4);
                    float ev[8] = { e0.x, e0.y, e0.z, e0.w, e1.x, e1.y, e1.z, e1.w };
                    a = g_alsrc[(size_t)ss * 8 + hh] + ald_hh;
                    #pragma unroll
                    for (int k = 0; k < 8; k++)
                        a = fmaf(ev[k], Ms[k * 8 + hh], a);
                    a = a > 0.f ? a : 0.2f * a;
                }
                wv = expf(a - m_hh) * ri_hh;
            }
            int   sj[4];
            float wj[4];
            #pragma unroll
            for (int j = 0; j < 4; j++) {
                sj[j] = __shfl_sync(0xffffffffu, ss, j * 8);
                wj[j] = __shfl_sync(0xffffffffu, wv, j * 8 + head);
            }
            uint4 v[4];
            #pragma unroll
            for (int j = 0; j < 4; j++)
                v[j] = *(const uint4*)(g_hh + (size_t)sj[j] * HC + lane * 8);
            #pragma unroll
            for (int j = 0; j < 4; j++) {
                float2 f0 = __half22float2(*(const __half2*)&v[j].x);
                float2 f1 = __half22float2(*(const __half2*)&v[j].y);
                float2 f2 = __half22float2(*(const __half2*)&v[j].z);
                float2 f3 = __half22float2(*(const __half2*)&v[j].w);
                acc[0] = fmaf(f0.x, wj[j], acc[0]); acc[1] = fmaf(f0.y, wj[j], acc[1]);
                acc[2] = fmaf(f1.x, wj[j], acc[2]); acc[3] = fmaf(f1.y, wj[j], acc[3]);
                acc[4] = fmaf(f2.x, wj[j], acc[4]); acc[5] = fmaf(f2.y, wj[j], acc[5]);
                acc[6] = fmaf(f3.x, wj[j], acc[6]); acc[7] = fmaf(f3.y, wj[j], acc[7]);
            }
        }
    }
    float* po = g_agg + (size_t)n * HC + lane * 8;
    *(float4*)(po)     = make_float4(acc[0], acc[1], acc[2], acc[3]);
    *(float4*)(po + 4) = make_float4(acc[4], acc[5], acc[6], acc[7]);
}

// ---------------- epilogue: y = relu(agg + b) @ LW + lb ------------------------
template <int NJ>
__global__ void __launch_bounds__(256)
k_epi(const float* __restrict__ bias, const float* __restrict__ LW,
      const float* __restrict__ lb)
{
    constexpr int NODES = 256 / NJ;
    __shared__ float rows[NODES * 260];
    __shared__ float LWt[NJ * 260];       // transposed, padded stride
    int t  = threadIdx.x;
    int n0 = blockIdx.x * NODES;

    for (int i = t; i < HC * NJ; i += 256) {
        int c = i / NJ, j = i % NJ;
        LWt[j * 260 + c] = LW[i];
    }
    for (int i = t; i < NODES * HC; i += 256) {
        int n = i >> 8, c = i & 255;
        float v = 0.f;
        if (n0 + n < NN) v = g_agg[(size_t)(n0 + n) * HC + c] + bias[c];
        rows[n * 260 + c] = fmaxf(v, 0.f);
    }
    __syncthreads();

    int n = t / NJ, j = t % NJ;
    if (n0 + n < NN) {
        float acc = lb[j];
        #pragma unroll
        for (int c4 = 0; c4 < 64; c4++) {
            float4 r  = *(const float4*)&rows[n * 260 + c4 * 4];
            float4 wv = *(const float4*)&LWt[j * 260 + c4 * 4];
            acc = fmaf(r.x, wv.x, acc);
            acc = fmaf(r.y, wv.y, acc);
            acc = fmaf(r.z, wv.z, acc);
            acc = fmaf(r.w, wv.w, acc);
        }
        if (NJ == 32) g_x [(size_t)(n0 + n) * 32 + j] = acc;
        else          g_x5[(size_t)(n0 + n) * 8  + j] = acc;
    }
}

// ---------------- classifier over label edges ---------------------------------
__global__ void __launch_bounds__(256)
k_clf(const int* __restrict__ eli, const float* __restrict__ ela,
      const float* __restrict__ cW, const float* __restrict__ cb,
      float* __restrict__ outp)
{
    __shared__ float Ws[128], Bs[8];
    if (threadIdx.x < 128) Ws[threadIdx.x] = cW[threadIdx.x];
    if (threadIdx.x < 8)   Bs[threadIdx.x] = cb[threadIdx.x];
    __syncthreads();
    int l = blockIdx.x * 256 + threadIdx.x;
    if (l >= LL) return;
    int u = eli[l], m = eli[LL + l];

    float4 u0 = *(const float4*)(g_x5 + (size_t)u * 8);
    float4 u1 = *(const float4*)(g_x5 + (size_t)u * 8 + 4);
    float4 m0 = *(const float4*)(g_x5 + (size_t)m * 8);
    float4 m1 = *(const float4*)(g_x5 + (size_t)m * 8 + 4);
    float4 a0 = *(const float4*)(ela + (size_t)l * 8);
    float4 a1 = *(const float4*)(ela + (size_t)l * 8 + 4);
    float xu[8] = { u0.x, u0.y, u0.z, u0.w, u1.x, u1.y, u1.z, u1.w };
    float xm[8] = { m0.x, m0.y, m0.z, m0.w, m1.x, m1.y, m1.z, m1.w };
    float ev[8] = { a0.x, a0.y, a0.z, a0.w, a1.x, a1.y, a1.z, a1.w };

    float dot = 0.f;
    #pragma unroll
    for (int j = 0; j < 8; j++) {
        float fu = Bs[j];
        #pragma unroll
        for (int k = 0; k < 8; k++) fu = fmaf(xu[k], Ws[k * 8 + j], fu);
        #pragma unroll
        for (int k = 0; k < 8; k++) fu = fmaf(ev[k], Ws[(8 + k) * 8 + j], fu);
        dot = fmaf(fu, xm[j], dot);
    }
    outp[l] = 1.f / (1.f + expf(-dot));
}

// ---------------- launch -------------------------------------------------------
extern "C" void kernel_launch(void* const* d_in, const int* in_sizes, int n_in,
                              void* d_out, int out_size)
{
    const int*   node_ids = (const int*)d_in[0];
    const int*   ei   = (const int*)d_in[1];
    const int*   eli  = (const int*)d_in[2];
    const float* ea   = (const float*)d_in[4];
    const float* ela  = (const float*)d_in[5];
    const float* emb  = (const float*)d_in[6];
    const float* W1   = (const float*)d_in[7];
    const float* as1  = (const float*)d_in[8];
    const float* ad1  = (const float*)d_in[9];
    const float* We1  = (const float*)d_in[10];
    const float* ae1  = (const float*)d_in[11];
    const float* b1   = (const float*)d_in[12];
    const float* l1W  = (const float*)d_in[13];
    const float* l1b  = (const float*)d_in[14];
    const float* W2   = (const float*)d_in[15];
    const float* as2  = (const float*)d_in[16];
    const float* ad2  = (const float*)d_in[17];
    const float* We2  = (const float*)d_in[18];
    const float* ae2  = (const float*)d_in[19];
    const float* b2   = (const float*)d_in[20];
    const float* l5W  = (const float*)d_in[21];
    const float* l5b  = (const float*)d_in[22];
    const float* cW   = (const float*)d_in[23];
    const float* cb   = (const float*)d_in[24];
    float* out = (float*)d_out;

    const int* srce = ei;
    const int* dste = ei + EE;

    const int GB_NODE = (NN + 31) / 32;            // 1563
    const int GB_EDGE = (EE + 255) / 256;          // 3125
    const int GB_FUSE = (NN + 7) / 8;              // 6250
    const int GB_N256 = (NN + 255) / 256;          // 196

    // CSR build (shared by both layers)
    k_zero_deg<<<GB_N256, 256>>>();
    k_hist<<<GB_EDGE, 256>>>(dste);
    k_scan<<<1, 1024>>>();
    k_scatter<<<GB_EDGE, 256>>>(srce, dste);

    k_precompute<<<2, 256>>>(W1, as1, ad1, We1, ae1, W2, as2, ad2, We2, ae2);

    // ---- layer 1 ----
    k_node<<<GB_NODE, 256>>>(emb, node_ids, W1, 0);
    k_fused<<<GB_FUSE, 256>>>(ea, 0);
    k_epi<32><<<(NN + 7) / 8, 256>>>(b1, l1W, l1b);

    // ---- layer 2 ----
    k_node<<<GB_NODE, 256>>>(nullptr, nullptr, W2, 1);
    k_fused<<<GB_FUSE, 256>>>(ea, 1);
    k_epi<8><<<(NN + 31) / 32, 256>>>(b2, l5W, l5b);

    // ---- classifier ----
    k_clf<<<(LL + 255) / 256, 256>>>(eli, ela, cW, cb, out);
}

// round 5
// speedup vs baseline: 1.2314x; 1.2314x over previous
#include <cuda_runtime.h>
#include <cuda_fp16.h>
#include <math.h>

#define NN  50000   // nodes
#define EE  800000  // edges
#define LL  100000  // label edges
#define HH  8       // heads
#define FD  32      // hidden
#define HC  256     // H*C

// ---------------- scratch (device globals) --------------------------------------
__device__ float  g_x[NN * FD];
__device__ __half g_hh[(size_t)NN * HC];
__device__ float  g_alsrc[NN * HH];
__device__ float  g_aldst[NN * HH];
__device__ float  g_alpha[(size_t)EE * HH]; // alpha (CSR order) -> ex after softmax
__device__ float  g_rinv[NN * HH];          // 1/denom per (node, head)
__device__ float  g_agg[(size_t)NN * HC];
__device__ float  g_x5[NN * HH];
__device__ float  g_Psrc[2][FD * HH];
__device__ float  g_Pdst[2][FD * HH];
__device__ float  g_M[2][HH * HH];
// CSR by destination
__device__ int g_deg[NN];
__device__ int g_rowptr[NN + 1];
__device__ int g_cursor[NN];
__device__ int g_srcp[EE];   // src node per CSR slot
__device__ int g_slot[EE];   // CSR slot per original edge

// ---------------- precompute both layers: P_src/P_dst [32,8], M [8,8] ----------
__global__ void k_precompute(const float* __restrict__ W1,  const float* __restrict__ as1,
                             const float* __restrict__ ad1, const float* __restrict__ We1,
                             const float* __restrict__ ae1,
                             const float* __restrict__ W2,  const float* __restrict__ as2,
                             const float* __restrict__ ad2, const float* __restrict__ We2,
                             const float* __restrict__ ae2)
{
    int layer = blockIdx.x;
    const float* W   = layer ? W2  : W1;
    const float* a_s = layer ? as2 : as1;
    const float* a_d = layer ? ad2 : ad1;
    const float* We  = layer ? We2 : We1;
    const float* a_e = layer ? ae2 : ae1;

    int t = threadIdx.x;           // 256 threads
    int f = t >> 3, h = t & 7;
    float ss = 0.f, sd = 0.f;
    #pragma unroll 8
    for (int c = 0; c < FD; c++) {
        float w = W[f * HC + h * FD + c];
        ss = fmaf(w, a_s[h * FD + c], ss);
        sd = fmaf(w, a_d[h * FD + c], sd);
    }
    g_Psrc[layer][f * HH + h] = ss;
    g_Pdst[layer][f * HH + h] = sd;
    if (t < 64) {
        int k = t >> 3;
        float sm = 0.f;
        #pragma unroll 8
        for (int c = 0; c < FD; c++)
            sm = fmaf(We[k * HC + h * FD + c], a_e[h * FD + c], sm);
        g_M[layer][k * HH + h] = sm;
    }
}

// ---------------- CSR build -----------------------------------------------------
__global__ void k_zero_deg(void) {
    int i = blockIdx.x * 256 + threadIdx.x;
    if (i < NN) g_deg[i] = 0;
}
__global__ void k_hist(const int* __restrict__ dst) {
    int e = blockIdx.x * 256 + threadIdx.x;
    if (e < EE) atomicAdd(&g_deg[dst[e]], 1);
}
__global__ void __launch_bounds__(1024)
k_scan(void) {
    const int CH = (NN + 1023) / 1024;   // 49
    __shared__ int sums[1024];
    int t = threadIdx.x;
    int base = t * CH;
    int s = 0;
    for (int i = 0; i < CH; i++) {
        int idx = base + i;
        if (idx < NN) s += g_deg[idx];
    }
    sums[t] = s;
    __syncthreads();
    for (int off = 1; off < 1024; off <<= 1) {
        int v = (t >= off) ? sums[t - off] : 0;
        __syncthreads();
        sums[t] += v;
        __syncthreads();
    }
    int run = (t > 0) ? sums[t - 1] : 0;
    for (int i = 0; i < CH; i++) {
        int idx = base + i;
        if (idx < NN) {
            g_rowptr[idx] = run;
            g_cursor[idx] = run;
            run += g_deg[idx];
        }
    }
    if (t == 1023) g_rowptr[NN] = run;
}
__global__ void k_scatter(const int* __restrict__ src, const int* __restrict__ dst) {
    int e = blockIdx.x * 256 + threadIdx.x;
    if (e >= EE) return;
    int d = dst[e];
    int slot = atomicAdd(&g_cursor[d], 1);
    g_srcp[slot] = src[e];   // scattered store
    g_slot[e]    = slot;     // coalesced store
}

// ---------------- node transform: h = x@W (fp16), al_src/al_dst ----------------
__global__ void __launch_bounds__(256)
k_node(const float* __restrict__ xin, const int* __restrict__ ids,
       const float* __restrict__ W, int layer)
{
    __shared__ float Ws[FD * HC];      // 32KB
    __shared__ float xs[32 * 36];
    __shared__ float Ps[FD * HH], Pd[FD * HH];
    int t  = threadIdx.x;
    int n0 = blockIdx.x * 32;

    for (int i = t; i < FD * HC; i += 256) Ws[i] = W[i];
    Ps[t] = g_Psrc[layer][t];
    Pd[t] = g_Pdst[layer][t];
    const float* xp = xin ? xin : g_x;
    for (int i = t; i < 32 * FD; i += 256) {
        int n = i >> 5, k = i & 31;
        int node = n0 + n;
        float v = 0.f;
        if (node < NN) {
            int r = ids ? ids[node] : node;
            v = xp[(size_t)r * FD + k];
        }
        xs[n * 36 + k] = v;
    }
    __syncthreads();

    float acc[32];
    #pragma unroll
    for (int n = 0; n < 32; n++) acc[n] = 0.f;
    #pragma unroll
    for (int kk = 0; kk < 8; kk++) {
        float w0 = Ws[(kk * 4 + 0) * HC + t];
        float w1 = Ws[(kk * 4 + 1) * HC + t];
        float w2 = Ws[(kk * 4 + 2) * HC + t];
        float w3 = Ws[(kk * 4 + 3) * HC + t];
        #pragma unroll
        for (int n = 0; n < 32; n++) {
            float4 xv = *(const float4*)&xs[n * 36 + kk * 4];
            acc[n] = fmaf(xv.x, w0, acc[n]);
            acc[n] = fmaf(xv.y, w1, acc[n]);
            acc[n] = fmaf(xv.z, w2, acc[n]);
            acc[n] = fmaf(xv.w, w3, acc[n]);
        }
    }
    #pragma unroll
    for (int n = 0; n < 32; n++)
        if (n0 + n < NN) g_hh[(size_t)(n0 + n) * HC + t] = __float2half(acc[n]);

    {
        int n = t >> 3, h = t & 7;
        if (n0 + n < NN) {
            float ss = 0.f, sd = 0.f;
            #pragma unroll
            for (int k = 0; k < FD; k++) {
                float xv = xs[n * 36 + k];
                ss = fmaf(xv, Ps[k * HH + h], ss);
                sd = fmaf(xv, Pd[k * HH + h], sd);
            }
            g_alsrc[(n0 + n) * HH + h] = ss;
            g_aldst[(n0 + n) * HH + h] = sd;
        }
    }
}

// ---------------- edge: alpha = lrelu(al_src[s]+al_dst[d]+ea@M) -> CSR slot -----
__global__ void __launch_bounds__(256)
k_edge_alpha(const int* __restrict__ src, const int* __restrict__ dst,
             const float* __restrict__ ea, int layer)
{
    __shared__ float Ms[64];
    if (threadIdx.x < 64) Ms[threadIdx.x] = g_M[layer][threadIdx.x];
    __syncthreads();
    int e = blockIdx.x * 256 + threadIdx.x;
    if (e >= EE) return;
    int s = src[e], d = dst[e];
    int p = g_slot[e];

    float4 e0 = *(const float4*)(ea + (size_t)e * 8);       // coalesced
    float4 e1 = *(const float4*)(ea + (size_t)e * 8 + 4);
    float4 s0 = *(const float4*)(g_alsrc + (size_t)s * 8);  // gather 32B
    float4 s1 = *(const float4*)(g_alsrc + (size_t)s * 8 + 4);
    float4 d0 = *(const float4*)(g_aldst + (size_t)d * 8);  // gather 32B
    float4 d1 = *(const float4*)(g_aldst + (size_t)d * 8 + 4);

    float al[8] = { s0.x + d0.x, s0.y + d0.y, s0.z + d0.z, s0.w + d0.w,
                    s1.x + d1.x, s1.y + d1.y, s1.z + d1.z, s1.w + d1.w };
    float ev[8] = { e0.x, e0.y, e0.z, e0.w, e1.x, e1.y, e1.z, e1.w };
    #pragma unroll
    for (int k = 0; k < 8; k++)
        #pragma unroll
        for (int h = 0; h < 8; h++)
            al[h] = fmaf(ev[k], Ms[k * 8 + h], al[h]);
    #pragma unroll
    for (int h = 0; h < 8; h++) al[h] = al[h] > 0.f ? al[h] : 0.2f * al[h];

    *(float4*)(g_alpha + (size_t)p * 8)     = make_float4(al[0], al[1], al[2], al[3]);
    *(float4*)(g_alpha + (size_t)p * 8 + 4) = make_float4(al[4], al[5], al[6], al[7]);
}

// ---------------- per-node softmax: max, then exp+sum (write ex, store rinv) ----
__global__ void __launch_bounds__(256)
k_softmax(void)
{
    int n    = (blockIdx.x * 256 + threadIdx.x) >> 5;
    int lane = threadIdx.x & 31;
    if (n >= NN) return;
    int r0 = g_rowptr[n], r1 = g_rowptr[n + 1];
    int deg = r1 - r0;
    if (deg == 0) return;

    int h  = lane & 7;       // head
    int eg = lane >> 3;      // edge group 0..3

    // pass 1: per-head max
    float m = -INFINITY;
    for (int i = eg; i < deg; i += 4)
        m = fmaxf(m, g_alpha[(size_t)(r0 + i) * 8 + h]);
    m = fmaxf(m, __shfl_xor_sync(0xffffffffu, m, 8));
    m = fmaxf(m, __shfl_xor_sync(0xffffffffu, m, 16));

    // pass 2: exp + sum, write ex in place
    float s = 0.f;
    for (int i = eg; i < deg; i += 4) {
        size_t idx = (size_t)(r0 + i) * 8 + h;
        float ex = expf(g_alpha[idx] - m);
        g_alpha[idx] = ex;
        s += ex;
    }
    s += __shfl_xor_sync(0xffffffffu, s, 8);
    s += __shfl_xor_sync(0xffffffffu, s, 16);
    if (lane < 8) g_rinv[(size_t)n * 8 + lane] = 1.f / (s + 1e-16f);
}

// ---------------- heavy: agg[n] = rinv * sum h[src]*ex  (warp/node, 8-edge MLP) -
__global__ void __launch_bounds__(256)
k_agg_csr(void)
{
    int n    = (blockIdx.x * 256 + threadIdx.x) >> 5;
    int lane = threadIdx.x & 31;
    if (n >= NN) return;
    int r0 = g_rowptr[n], r1 = g_rowptr[n + 1];

    int head = lane >> 2;      // head owning cols lane*8 .. lane*8+7
    float acc0 = 0.f, acc1 = 0.f, acc2 = 0.f, acc3 = 0.f;
    float acc4 = 0.f, acc5 = 0.f, acc6 = 0.f, acc7 = 0.f;

    for (int p = r0; p < r1; p += 8) {
        int cnt = r1 - p;
        // 8 edges' weights = 64 consecutive floats; two coalesced lane loads
        size_t wbase = (size_t)p * 8;
        size_t wlim  = (size_t)r1 * 8 - 1;
        size_t ia = wbase + lane;      if (ia > wlim) ia = wlim;
        size_t ib = wbase + 32 + lane; if (ib > wlim) ib = wlim;
        float w_a = g_alpha[ia];
        float w_b = g_alpha[ib];

        int sj[8];
        #pragma unroll
        for (int j = 0; j < 8; j++) {
            int pp = p + j; if (pp >= r1) pp = r1 - 1;
            sj[j] = g_srcp[pp];
        }
        // issue all gathers back-to-back (MLP=8 per lane)
        uint4 v[8];
        #pragma unroll
        for (int j = 0; j < 8; j++)
            v[j] = *(const uint4*)(g_hh + (size_t)sj[j] * HC + lane * 8);
        #pragma unroll
        for (int j = 0; j < 8; j++) {
            float w = __shfl_sync(0xffffffffu, (j < 4) ? w_a : w_b,
                                  (j & 3) * 8 + head);
            if (j >= cnt) w = 0.f;
            float2 f0 = __half22float2(*(const __half2*)&v[j].x);
            float2 f1 = __half22float2(*(const __half2*)&v[j].y);
            float2 f2 = __half22float2(*(const __half2*)&v[j].z);
            float2 f3 = __half22float2(*(const __half2*)&v[j].w);
            acc0 = fmaf(f0.x, w, acc0); acc1 = fmaf(f0.y, w, acc1);
            acc2 = fmaf(f1.x, w, acc2); acc3 = fmaf(f1.y, w, acc3);
            acc4 = fmaf(f2.x, w, acc4); acc5 = fmaf(f2.y, w, acc5);
            acc6 = fmaf(f3.x, w, acc6); acc7 = fmaf(f3.y, w, acc7);
        }
    }
    float rinv = (r0 < r1) ? g_rinv[(size_t)n * 8 + head] : 0.f;
    float* po = g_agg + (size_t)n * HC + lane * 8;
    *(float4*)(po)     = make_float4(acc0 * rinv, acc1 * rinv, acc2 * rinv, acc3 * rinv);
    *(float4*)(po + 4) = make_float4(acc4 * rinv, acc5 * rinv, acc6 * rinv, acc7 * rinv);
}

// ---------------- epilogue: y = relu(agg + b) @ LW + lb ------------------------
template <int NJ>
__global__ void __launch_bounds__(256)
k_epi(const float* __restrict__ bias, const float* __restrict__ LW,
      const float* __restrict__ lb)
{
    constexpr int NODES = 256 / NJ;
    __shared__ float rows[NODES * 260];
    __shared__ float LWt[NJ * 260];       // transposed, padded stride
    int t  = threadIdx.x;
    int n0 = blockIdx.x * NODES;

    for (int i = t; i < HC * NJ; i += 256) {
        int c = i / NJ, j = i % NJ;
        LWt[j * 260 + c] = LW[i];
    }
    for (int i = t; i < NODES * HC; i += 256) {
        int n = i >> 8, c = i & 255;
        float v = 0.f;
        if (n0 + n < NN) v = g_agg[(size_t)(n0 + n) * HC + c] + bias[c];
        rows[n * 260 + c] = fmaxf(v, 0.f);
    }
    __syncthreads();

    int n = t / NJ, j = t % NJ;
    if (n0 + n < NN) {
        float acc = lb[j];
        #pragma unroll
        for (int c4 = 0; c4 < 64; c4++) {
            float4 r  = *(const float4*)&rows[n * 260 + c4 * 4];
            float4 wv = *(const float4*)&LWt[j * 260 + c4 * 4];
            acc = fmaf(r.x, wv.x, acc);
            acc = fmaf(r.y, wv.y, acc);
            acc = fmaf(r.z, wv.z, acc);
            acc = fmaf(r.w, wv.w, acc);
        }
        if (NJ == 32) g_x [(size_t)(n0 + n) * 32 + j] = acc;
        else          g_x5[(size_t)(n0 + n) * 8  + j] = acc;
    }
}

// ---------------- classifier over label edges ---------------------------------
__global__ void __launch_bounds__(256)
k_clf(const int* __restrict__ eli, const float* __restrict__ ela,
      const float* __restrict__ cW, const float* __restrict__ cb,
      float* __restrict__ outp)
{
    __shared__ float Ws[128], Bs[8];
    if (threadIdx.x < 128) Ws[threadIdx.x] = cW[threadIdx.x];
    if (threadIdx.x < 8)   Bs[threadIdx.x] = cb[threadIdx.x];
    __syncthreads();
    int l = blockIdx.x * 256 + threadIdx.x;
    if (l >= LL) return;
    int u = eli[l], m = eli[LL + l];

    float4 u0 = *(const float4*)(g_x5 + (size_t)u * 8);
    float4 u1 = *(const float4*)(g_x5 + (size_t)u * 8 + 4);
    float4 m0 = *(const float4*)(g_x5 + (size_t)m * 8);
    float4 m1 = *(const float4*)(g_x5 + (size_t)m * 8 + 4);
    float4 a0 = *(const float4*)(ela + (size_t)l * 8);
    float4 a1 = *(const float4*)(ela + (size_t)l * 8 + 4);
    float xu[8] = { u0.x, u0.y, u0.z, u0.w, u1.x, u1.y, u1.z, u1.w };
    float xm[8] = { m0.x, m0.y, m0.z, m0.w, m1.x, m1.y, m1.z, m1.w };
    float ev[8] = { a0.x, a0.y, a0.z, a0.w, a1.x, a1.y, a1.z, a1.w };

    float dot = 0.f;
    #pragma unroll
    for (int j = 0; j < 8; j++) {
        float fu = Bs[j];
        #pragma unroll
        for (int k = 0; k < 8; k++) fu = fmaf(xu[k], Ws[k * 8 + j], fu);
        #pragma unroll
        for (int k = 0; k < 8; k++) fu = fmaf(ev[k], Ws[(8 + k) * 8 + j], fu);
        dot = fmaf(fu, xm[j], dot);
    }
    outp[l] = 1.f / (1.f + expf(-dot));
}

// ---------------- launch -------------------------------------------------------
extern "C" void kernel_launch(void* const* d_in, const int* in_sizes, int n_in,
                              void* d_out, int out_size)
{
    const int*   node_ids = (const int*)d_in[0];
    const int*   ei   = (const int*)d_in[1];
    const int*   eli  = (const int*)d_in[2];
    const float* ea   = (const float*)d_in[4];
    const float* ela  = (const float*)d_in[5];
    const float* emb  = (const float*)d_in[6];
    const float* W1   = (const float*)d_in[7];
    const float* as1  = (const float*)d_in[8];
    const float* ad1  = (const float*)d_in[9];
    const float* We1  = (const float*)d_in[10];
    const float* ae1  = (const float*)d_in[11];
    const float* b1   = (const float*)d_in[12];
    const float* l1W  = (const float*)d_in[13];
    const float* l1b  = (const float*)d_in[14];
    const float* W2   = (const float*)d_in[15];
    const float* as2  = (const float*)d_in[16];
    const float* ad2  = (const float*)d_in[17];
    const float* We2  = (const float*)d_in[18];
    const float* ae2  = (const float*)d_in[19];
    const float* b2   = (const float*)d_in[20];
    const float* l5W  = (const float*)d_in[21];
    const float* l5b  = (const float*)d_in[22];
    const float* cW   = (const float*)d_in[23];
    const float* cb   = (const float*)d_in[24];
    float* out = (float*)d_out;

    const int* srce = ei;
    const int* dste = ei + EE;

    const int GB_NODE = (NN + 31) / 32;            // 1563
    const int GB_EDGE = (EE + 255) / 256;          // 3125
    const int GB_WARP = (NN * 32 + 255) / 256;     // 6250 (warp per node)
    const int GB_N256 = (NN + 255) / 256;          // 196

    // CSR build (shared by both layers)
    k_zero_deg<<<GB_N256, 256>>>();
    k_hist<<<GB_EDGE, 256>>>(dste);
    k_scan<<<1, 1024>>>();
    k_scatter<<<GB_EDGE, 256>>>(srce, dste);

    k_precompute<<<2, 256>>>(W1, as1, ad1, We1, ae1, W2, as2, ad2, We2, ae2);

    // ---- layer 1 ----
    k_node<<<GB_NODE, 256>>>(emb, node_ids, W1, 0);
    k_edge_alpha<<<GB_EDGE, 256>>>(srce, dste, ea, 0);
    k_softmax<<<GB_WARP, 256>>>();
    k_agg_csr<<<GB_WARP, 256>>>();
    k_epi<32><<<(NN + 7) / 8, 256>>>(b1, l1W, l1b);

    // ---- layer 2 ----
    k_node<<<GB_NODE, 256>>>(nullptr, nullptr, W2, 1);
    k_edge_alpha<<<GB_EDGE, 256>>>(srce, dste, ea, 1);
    k_softmax<<<GB_WARP, 256>>>();
    k_agg_csr<<<GB_WARP, 256>>>();
    k_epi<8><<<(NN + 31) / 32, 256>>>(b2, l5W, l5b);

    // ---- classifier ----
    k_clf<<<(LL + 255) / 256, 256>>>(eli, ela, cW, cb, out);
}